// round 15
// baseline (speedup 1.0000x reference)
#include <cuda_runtime.h>
#include <cuda_bf16.h>
#include <cstdint>

// Problem constants: B=1, C=512, H=W=64, patch 3x3 reflect-padded.
#define HW    4096
#define NC    512
#define KT    1536          // 3-term bf16 split: [hi|lo|hi] x [hi|hi|lo]
#define BM    128
#define BN    128
#define BKC   16
#define KSPL  16            // split-K factor for gram
#define NTILE 10            // triangular 128x128 tiles of 512x512

// k_mma: block 128(m) x 128(n), 8 warps as 2(m) x 4(n), warp tile 64x32,
// BK=64, 3-stage cp.async, 2 CTAs/SM.
#define MMA_BM 128
#define MMA_BN 128
#define STAGES 3
#define LDA    72           // padded smem row (bf16): 64 data + 8 pad = 144B

// k_agg tiling: 8 i per block (2 iy x 4 ix), 8 j-bands of 512
#define AGG_SMEM (24 * 640 * 4)   // 61440 bytes

typedef unsigned long long u64;

// ---------------- scratch (static __device__, no allocation) ----------------
__device__ __align__(16) float g_ssP[16][2][HW];   // 32-channel-group ss partials
__device__ __align__(16) float g_cnorm[HW];
__device__ __align__(16) float g_snorm[HW];
__device__ int   g_idx[HW];
__device__ __align__(128) __nv_bfloat16 g_Abf[(size_t)HW * KT];   // content split, m-major
__device__ __align__(128) __nv_bfloat16 g_Bbf[(size_t)HW * KT];   // style split, n-major
__device__ __align__(16) float g_P[(size_t)HW * HW];              // C^T S scores (64 MB)
__device__ __align__(16) float g_Y[NC * 2 * HW];
__device__ __align__(16) float g_Gp[KSPL * NTILE * BM * BN];
__device__ __align__(16) float g_partial[NTILE * KSPL];
__device__ float g_msum;

__device__ __forceinline__ int refl(int t) {
    return t < 0 ? -t : (t >= 64 ? 126 - t : t);
}

// packed fp32x2 helpers (gram kernels)
__device__ __forceinline__ u64 pk2(float x) {
    u64 r;
    asm("mov.b64 %0, {%1, %1};" : "=l"(r) : "r"(__float_as_uint(x)));
    return r;
}
__device__ __forceinline__ void ffma2(u64& d, u64 a, u64 b) {
    asm("fma.rn.f32x2 %0, %1, %2, %0;" : "+l"(d) : "l"(a), "l"(b));
}
__device__ __forceinline__ float lo32(u64 v) { return __uint_as_float((unsigned)v); }
__device__ __forceinline__ float hi32(u64 v) { return __uint_as_float((unsigned)(v >> 32)); }

__device__ __forceinline__ uint32_t smem_u32(const void* p) {
    uint32_t a;
    asm("{ .reg .u64 t; cvta.to.shared.u64 t, %1; cvt.u32.u64 %0, t; }" : "=r"(a) : "l"(p));
    return a;
}
__device__ __forceinline__ void cp16(uint32_t saddr, const void* g) {
    asm volatile("cp.async.cg.shared.global [%0], [%1], 16;" :: "r"(saddr), "l"(g));
}

// ---------------- 0) bf16 split + transpose + fused ss partials -------------
__global__ void k_conv(const float* __restrict__ Cf, const float* __restrict__ Sf) {
    __shared__ float tile[32][33];
    const int which = blockIdx.z;
    const float* src = which ? Sf : Cf;
    __nv_bfloat16* dst = which ? g_Bbf : g_Abf;
    const int m0 = blockIdx.x * 32, c0 = blockIdx.y * 32;
    const int tx = threadIdx.x, ty = threadIdx.y;   // 32 x 8

    #pragma unroll
    for (int r = 0; r < 4; ++r)
        tile[ty + 8 * r][tx] = src[(size_t)(c0 + ty + 8 * r) * HW + m0 + tx];
    __syncthreads();
    #pragma unroll
    for (int r = 0; r < 4; ++r) {
        const int m = m0 + ty + 8 * r;
        const int c = c0 + tx;
        const float x = tile[tx][ty + 8 * r];
        const __nv_bfloat16 hi = __float2bfloat16(x);
        const __nv_bfloat16 lo = __float2bfloat16(x - __bfloat162float(hi));
        __nv_bfloat16* row = dst + (size_t)m * KT;
        if (which == 0) {       // A' = [hi | lo | hi]
            row[c] = hi; row[512 + c] = lo; row[1024 + c] = hi;
        } else {                // B' = [hi | hi | lo]
            row[c] = hi; row[512 + c] = hi; row[1024 + c] = lo;
        }
        float s = x * x;
        #pragma unroll
        for (int o = 16; o > 0; o >>= 1)
            s += __shfl_down_sync(0xffffffffu, s, o);
        if (tx == 0) g_ssP[blockIdx.y][which][m] = s;
    }
}

// ---------------- 1) patch norms + mask sum (merged) ------------------------
__global__ void k_norm(const float* __restrict__ Mk) {
    const int b = blockIdx.x;
    const int t = threadIdx.x;
    if (b < 16) {
        const int i = b * 256 + t;
        const int yy = i >> 6, xx = i & 63;
        float sc = 0.f, ss = 0.f;
        #pragma unroll
        for (int dh = -1; dh <= 1; ++dh)
            #pragma unroll
            for (int dw = -1; dw <= 1; ++dw) {
                const int p = refl(yy + dh) * 64 + refl(xx + dw);
                float a = 0.f, c = 0.f;
                #pragma unroll
                for (int s = 0; s < 16; ++s) {
                    a += g_ssP[s][0][p];
                    c += g_ssP[s][1][p];
                }
                sc += a;
                ss += c;
            }
        g_cnorm[i] = sqrtf(sc);
        g_snorm[i] = sqrtf(ss);
    } else {
        __shared__ float red[256];
        float s = 0.f;
        #pragma unroll
        for (int k = 0; k < 16; ++k) s += Mk[t + 256 * k];
        red[t] = s;
        __syncthreads();
        for (int o = 128; o > 0; o >>= 1) {
            if (t < o) red[t] += red[t + o];
            __syncthreads();
        }
        if (t == 0) g_msum = red[0];
    }
}

// ---------------- 2) P = A' B'^T via mma.sync bf16, BK=64, 3-stage ---------
#define ASZ (MMA_BM * LDA)            // 9216 elems per A stage buffer
#define BSZ (MMA_BN * LDA)
#define SMEM_MMA_BYTES ((STAGES * (ASZ + BSZ)) * 2)   // 110592 bytes

__global__ __launch_bounds__(256, 2) void k_mma() {
    extern __shared__ __nv_bfloat16 smem[];

    const int tid = threadIdx.x, wid = tid >> 5, lane = tid & 31;
    const int i0 = blockIdx.x * MMA_BM, j0 = blockIdx.y * MMA_BN;
    const int wm = (wid >> 2) * 64, wn = (wid & 3) * 32;

    const int lrow = tid >> 3, lseg = tid & 7;
    const __nv_bfloat16* gA = g_Abf + (size_t)(i0 + lrow) * KT + lseg * 8;
    const __nv_bfloat16* gB = g_Bbf + (size_t)(j0 + lrow) * KT + lseg * 8;
    const int so = lrow * LDA + lseg * 8;

    uint32_t sA[STAGES], sB[STAGES];
    #pragma unroll
    for (int st = 0; st < STAGES; ++st) {
        sA[st] = smem_u32(smem + st * (ASZ + BSZ));
        sB[st] = smem_u32(smem + st * (ASZ + BSZ) + ASZ);
    }

    const int a_r = lane & 15, a_c8 = (lane >> 4) * 8;                          // A x4
    const int b_r = (lane >> 4) * 8 + (lane & 7), b_c8 = ((lane >> 3) & 1) * 8; // B x4 (n16)

    float acc[4][4][4];
    #pragma unroll
    for (int mf = 0; mf < 4; ++mf)
        #pragma unroll
        for (int nf = 0; nf < 4; ++nf)
            #pragma unroll
            for (int q = 0; q < 4; ++q) acc[mf][nf][q] = 0.f;

    const int NSTAGE = KT / 64;   // 24

    #pragma unroll
    for (int s = 0; s < STAGES - 1; ++s) {
        const int cb = s * 64;
        const uint32_t a0 = sA[s] + (uint32_t)(so * 2);
        const uint32_t b0 = sB[s] + (uint32_t)(so * 2);
        #pragma unroll
        for (int r = 0; r < 4; ++r) {
            cp16(a0 + r * 32 * LDA * 2, gA + cb + (size_t)(r * 32) * KT);
            cp16(b0 + r * 32 * LDA * 2, gB + cb + (size_t)(r * 32) * KT);
        }
        asm volatile("cp.async.commit_group;" ::: "memory");
    }

    for (int s = 0; s < NSTAGE; ++s) {
        asm volatile("cp.async.wait_group %0;" :: "n"(STAGES - 2) : "memory");
        __syncthreads();

        if (s + STAGES - 1 < NSTAGE) {
            const int ns = s + STAGES - 1;
            const int buf = ns % STAGES;
            const int cb = ns * 64;
            const uint32_t a0 = sA[buf] + (uint32_t)(so * 2);
            const uint32_t b0 = sB[buf] + (uint32_t)(so * 2);
            #pragma unroll
            for (int r = 0; r < 4; ++r) {
                cp16(a0 + r * 32 * LDA * 2, gA + cb + (size_t)(r * 32) * KT);
                cp16(b0 + r * 32 * LDA * 2, gB + cb + (size_t)(r * 32) * KT);
            }
        }
        asm volatile("cp.async.commit_group;" ::: "memory");

        const int cur = s % STAGES;
        #pragma unroll
        for (int k0 = 0; k0 < 64; k0 += 16) {
            uint32_t b[4][2];
            #pragma unroll
            for (int np = 0; np < 2; ++np) {
                const uint32_t addr = sB[cur] +
                    (uint32_t)(((wn + np * 16 + b_r) * LDA + k0 + b_c8) * 2);
                asm volatile("ldmatrix.sync.aligned.m8n8.x4.shared.b16 {%0, %1, %2, %3}, [%4];"
                             : "=r"(b[2 * np][0]), "=r"(b[2 * np][1]),
                               "=r"(b[2 * np + 1][0]), "=r"(b[2 * np + 1][1])
                             : "r"(addr));
            }
            #pragma unroll
            for (int mf = 0; mf < 4; ++mf) {
                uint32_t a0, a1, a2, a3;
                const uint32_t addr = sA[cur] +
                    (uint32_t)(((wm + mf * 16 + a_r) * LDA + k0 + a_c8) * 2);
                asm volatile("ldmatrix.sync.aligned.m8n8.x4.shared.b16 {%0, %1, %2, %3}, [%4];"
                             : "=r"(a0), "=r"(a1), "=r"(a2), "=r"(a3) : "r"(addr));
                #pragma unroll
                for (int nf = 0; nf < 4; ++nf) {
                    asm volatile(
                        "mma.sync.aligned.m16n8k16.row.col.f32.bf16.bf16.f32 "
                        "{%0, %1, %2, %3}, {%4, %5, %6, %7}, {%8, %9}, {%0, %1, %2, %3};"
                        : "+f"(acc[mf][nf][0]), "+f"(acc[mf][nf][1]),
                          "+f"(acc[mf][nf][2]), "+f"(acc[mf][nf][3])
                        : "r"(a0), "r"(a1), "r"(a2), "r"(a3),
                          "r"(b[nf][0]), "r"(b[nf][1]));
                }
            }
        }
    }

    const int er = lane >> 2, ec = (lane & 3) * 2;
    #pragma unroll
    for (int mf = 0; mf < 4; ++mf) {
        const int row = i0 + wm + mf * 16 + er;
        #pragma unroll
        for (int nf = 0; nf < 4; ++nf) {
            const int col = j0 + wn + nf * 8 + ec;
            *(float2*)&g_P[(size_t)row * HW + col] =
                make_float2(acc[mf][nf][0], acc[mf][nf][1]);
            *(float2*)&g_P[(size_t)(row + 8) * HW + col] =
                make_float2(acc[mf][nf][2], acc[mf][nf][3]);
        }
    }
}

// ---------------- 3) smem-tiled 9-shift aggregate + argmax ------------------
// Block: 8 content pixels (iy in {y0,y0+1}, ix in {x0..x0+3}); 8 j-bands of 512.
// Tile: 24 content P-rows (4 cy x 6 cx) x 10 j-image rows x 64 = 61440 B.
__global__ __launch_bounds__(256, 2) void k_agg() {
    extern __shared__ float tl[];      // [24][640]
    const int t = threadIdx.x;
    const int bx = blockIdx.x & 15, by = blockIdx.x >> 4;
    const int x0 = bx * 4, y0 = by * 2;

    const int jx = t & 63;
    const int rjx[3] = { refl(jx - 1), jx, refl(jx + 1) };
    const int jrow = t >> 6;           // 0..3

    float cn[2][4];
    #pragma unroll
    for (int q = 0; q < 2; ++q)
        #pragma unroll
        for (int p = 0; p < 4; ++p)
            cn[q][p] = g_cnorm[(y0 + q) * 64 + x0 + p];

    float best[2][4];
    int   bidx[2][4];
    #pragma unroll
    for (int q = 0; q < 2; ++q)
        #pragma unroll
        for (int p = 0; p < 4; ++p) { best[q][p] = -1e30f; bidx[q][p] = 0x7fffffff; }

    for (int band = 0; band < 8; ++band) {
        const int b0 = band * 8;       // j image-row base
        __syncthreads();               // protect tile from previous band's readers

        // stage tile: 3840 float4, 15 per thread; coalesced 64-float segments
        #pragma unroll
        for (int w = 0; w < 15; ++w) {
            const int idx4 = t + 256 * w;
            const int row = idx4 / 160;              // 0..23
            const int c4  = idx4 - row * 160;
            const int v   = c4 >> 4;                 // 0..9 j-image row slot
            const int x4  = (c4 & 15) << 2;
            const int cy = refl(y0 - 1 + (row / 6));
            const int cx = refl(x0 - 1 + (row % 6));
            const int jy = refl(b0 - 1 + v);
            *(float4*)&tl[row * 640 + v * 64 + x4] =
                *(const float4*)&g_P[((size_t)(cy * 64 + cx) << 12) + jy * 64 + x4];
        }
        __syncthreads();

        float acc[2][4][2] = {};
        #pragma unroll
        for (int dh = 0; dh < 3; ++dh) {
            const int v0 = (jrow + dh) * 64;
            const int v1 = v0 + 256;               // (jrow + 4 + dh) * 64
            #pragma unroll
            for (int dw = 0; dw < 3; ++dw) {
                const int c0 = v0 + rjx[dw];
                const int c1 = v1 + rjx[dw];
                #pragma unroll
                for (int q = 0; q < 2; ++q)
                    #pragma unroll
                    for (int p = 0; p < 4; ++p) {
                        const float* rp = &tl[((q + dh) * 6 + p + dw) * 640];
                        acc[q][p][0] += rp[c0];
                        acc[q][p][1] += rp[c1];
                    }
            }
        }

        const int j0 = b0 * 64 + t;
        const int j1 = j0 + 256;
        const float sn0 = g_snorm[j0], sn1 = g_snorm[j1];
        #pragma unroll
        for (int q = 0; q < 2; ++q)
            #pragma unroll
            for (int p = 0; p < 4; ++p) {
                const float v0 = __fdividef(acc[q][p][0], cn[q][p] * sn0 + 1e-9f);
                const float v1 = __fdividef(acc[q][p][1], cn[q][p] * sn1 + 1e-9f);
                if (v0 > best[q][p]) { best[q][p] = v0; bidx[q][p] = j0; }
                if (v1 > best[q][p]) { best[q][p] = v1; bidx[q][p] = j1; }
            }
    }

    // cross-thread argmax reduction (reuse tile smem)
    __syncthreads();
    float* redv = tl;                      // 8 x 256 floats
    int*   redi = (int*)(tl + 2048);       // 8 x 256 ints
    #pragma unroll
    for (int q = 0; q < 2; ++q)
        #pragma unroll
        for (int p = 0; p < 4; ++p) {
            redv[(q * 4 + p) * 256 + t] = best[q][p];
            redi[(q * 4 + p) * 256 + t] = bidx[q][p];
        }
    __syncthreads();
    for (int o = 128; o > 0; o >>= 1) {
        if (t < o) {
            #pragma unroll
            for (int i = 0; i < 8; ++i) {
                const float v2 = redv[i * 256 + t + o];
                const int   j2 = redi[i * 256 + t + o];
                if (v2 > redv[i * 256 + t] ||
                    (v2 == redv[i * 256 + t] && j2 < redi[i * 256 + t])) {
                    redv[i * 256 + t] = v2;
                    redi[i * 256 + t] = j2;
                }
            }
        }
        __syncthreads();
    }
    if (t < 8) {
        const int q = t >> 2, p = t & 3;
        g_idx[(y0 + q) * 64 + x0 + p] = redi[t * 256];
    }
}

// ---------------- 4) build Y ----------------
__global__ void k_gather(const float* __restrict__ Sf, const float* __restrict__ If,
                         const float* __restrict__ Mk) {
    int e = blockIdx.x * 256 + threadIdx.x;
    int c = e >> 13, k = e & 8191;
    if (k < HW) {
        g_Y[e] = If[(c << 12) + k] * Mk[k];
    } else {
        int j = k - HW;
        g_Y[e] = Sf[(c << 12) + g_idx[j]] * Mk[j];
    }
}

// ---------------- 5a) split-K signed gram partials (coalesced loader) -------
__constant__ int c_bx[NTILE] = {0,0,0,0,1,1,1,2,2,3};
__constant__ int c_by[NTILE] = {0,1,2,3,1,2,3,2,3,3};

__global__ __launch_bounds__(256, 2) void k_gramp() {
    __shared__ __align__(16) float Asg[BKC][BM + 4];
    __shared__ __align__(16) float Bsg[BKC][BN + 4];

    const int t  = threadIdx.x;
    const int tx = t & 15, ty = t >> 4;
    const int m0 = c_bx[blockIdx.x] * BM;
    const int n0 = c_by[blockIdx.x] * BN;
    const int kbase = blockIdx.y * (2 * HW / KSPL);
    const float sgn = (kbase >= HW) ? -1.0f : 1.0f;

    const int kk = t & 15;
    const int mr = t >> 4;

    u64 acc[8][4];
    #pragma unroll
    for (int mi = 0; mi < 8; ++mi)
        #pragma unroll
        for (int p = 0; p < 4; ++p) acc[mi][p] = 0ull;

    for (int k0 = kbase; k0 < kbase + 2 * HW / KSPL; k0 += BKC) {
        #pragma unroll
        for (int r = 0; r < 8; ++r) {
            const int row = mr + 16 * r;
            Asg[kk][row] = g_Y[(size_t)(m0 + row) * (2 * HW) + k0 + kk];
            Bsg[kk][row] = g_Y[(size_t)(n0 + row) * (2 * HW) + k0 + kk] * sgn;
        }
        __syncthreads();
        #pragma unroll
        for (int k = 0; k < BKC; ++k) {
            const float4 a0 = *(const float4*)&Asg[k][ty << 2];
            const float4 a1 = *(const float4*)&Asg[k][64 + (ty << 2)];
            const ulonglong2 b0 = *(const ulonglong2*)&Bsg[k][tx << 2];
            const ulonglong2 b1 = *(const ulonglong2*)&Bsg[k][64 + (tx << 2)];
            const u64 p0 = pk2(a0.x), p1 = pk2(a0.y), p2 = pk2(a0.z), p3 = pk2(a0.w);
            const u64 p4 = pk2(a1.x), p5 = pk2(a1.y), p6 = pk2(a1.z), p7 = pk2(a1.w);
            ffma2(acc[0][0], p0, b0.x); ffma2(acc[0][1], p0, b0.y);
            ffma2(acc[0][2], p0, b1.x); ffma2(acc[0][3], p0, b1.y);
            ffma2(acc[1][0], p1, b0.x); ffma2(acc[1][1], p1, b0.y);
            ffma2(acc[1][2], p1, b1.x); ffma2(acc[1][3], p1, b1.y);
            ffma2(acc[2][0], p2, b0.x); ffma2(acc[2][1], p2, b0.y);
            ffma2(acc[2][2], p2, b1.x); ffma2(acc[2][3], p2, b1.y);
            ffma2(acc[3][0], p3, b0.x); ffma2(acc[3][1], p3, b0.y);
            ffma2(acc[3][2], p3, b1.x); ffma2(acc[3][3], p3, b1.y);
            ffma2(acc[4][0], p4, b0.x); ffma2(acc[4][1], p4, b0.y);
            ffma2(acc[4][2], p4, b1.x); ffma2(acc[4][3], p4, b1.y);
            ffma2(acc[5][0], p5, b0.x); ffma2(acc[5][1], p5, b0.y);
            ffma2(acc[5][2], p5, b1.x); ffma2(acc[5][3], p5, b1.y);
            ffma2(acc[6][0], p6, b0.x); ffma2(acc[6][1], p6, b0.y);
            ffma2(acc[6][2], p6, b1.x); ffma2(acc[6][3], p6, b1.y);
            ffma2(acc[7][0], p7, b0.x); ffma2(acc[7][1], p7, b0.y);
            ffma2(acc[7][2], p7, b1.x); ffma2(acc[7][3], p7, b1.y);
        }
        __syncthreads();
    }

    float* dst = g_Gp + ((size_t)(blockIdx.y * NTILE + blockIdx.x) << 14);
    #pragma unroll
    for (int mi = 0; mi < 8; ++mi) {
        const int m_local = (mi < 4) ? (ty << 2) + mi : 64 + (ty << 2) + (mi - 4);
        #pragma unroll
        for (int p = 0; p < 4; ++p) {
            const int nb = (p < 2) ? (tx << 2) + 2 * p : 64 + (tx << 2) + 2 * (p - 2);
            *(float2*)&dst[m_local * BN + nb] = make_float2(lo32(acc[mi][p]), hi32(acc[mi][p]));
        }
    }
}

// ---------------- 5b) reduce split-K partials ----------------
__global__ void k_gramr() {
    __shared__ float red[256];
    const int t = threadIdx.x;
    const int tile = blockIdx.x;
    const int e0 = blockIdx.y * 1024 + t * 4;
    const float w = (c_bx[tile] == c_by[tile]) ? 1.0f : 2.0f;

    float4 d = make_float4(0.f, 0.f, 0.f, 0.f);
    #pragma unroll
    for (int ks = 0; ks < KSPL; ++ks) {
        const float4 v = *(const float4*)&g_Gp[((size_t)(ks * NTILE + tile) << 14) + e0];
        d.x += v.x; d.y += v.y; d.z += v.z; d.w += v.w;
    }
    red[t] = (d.x * d.x + d.y * d.y + d.z * d.z + d.w * d.w) * w;
    __syncthreads();
    for (int o = 128; o > 0; o >>= 1) {
        if (t < o) red[t] += red[t + o];
        __syncthreads();
    }
    if (t == 0) g_partial[tile * 16 + blockIdx.y] = red[0];
}

// ---------------- 6) final loss ----------------
__global__ void k_loss(float* __restrict__ out) {
    __shared__ float red[160];
    int t = threadIdx.x;          // blockDim.x == 160
    red[t] = g_partial[t];
    __syncthreads();
    if (t == 0) {
        float s = 0.f;
        for (int i = 0; i < NTILE * KSPL; ++i) s += red[i];
        const float ms = g_msum;
        out[0] = s / (ms * ms) / (float)(NC * NC) * 100.0f;
    }
}

// ---------------- launch ----------------
extern "C" void kernel_launch(void* const* d_in, const int* in_sizes, int n_in,
                              void* d_out, int out_size) {
    const float* Cf = (const float*)d_in[0];
    const float* Sf = (const float*)d_in[1];
    const float* If = (const float*)d_in[2];
    const float* Mk = (const float*)d_in[3];

    static int smem_set = 0;
    if (!smem_set) {
        cudaFuncSetAttribute(k_mma, cudaFuncAttributeMaxDynamicSharedMemorySize,
                             SMEM_MMA_BYTES);
        cudaFuncSetAttribute(k_agg, cudaFuncAttributeMaxDynamicSharedMemorySize,
                             AGG_SMEM);
        smem_set = 1;
    }

    dim3 gc(HW / 32, NC / 32, 2);
    k_conv<<<gc, dim3(32, 8)>>>(Cf, Sf);           // 0  (ss partials fused)
    k_norm<<<17, 256>>>(Mk);                       // 1  (norm + msum merged)
    dim3 gm(HW / MMA_BM, HW / MMA_BN);
    k_mma<<<gm, 256, SMEM_MMA_BYTES>>>();          // 2
    k_agg<<<512, 256, AGG_SMEM>>>();               // 3  (ncu capture slot)
    k_gather<<<(NC * 2 * HW) / 256, 256>>>(Sf, If, Mk);  // 4
    dim3 ggp(NTILE, KSPL);
    k_gramp<<<ggp, 256>>>();                       // 5
    dim3 ggr(NTILE, 16);
    k_gramr<<<ggr, 256>>>();                       // 6
    k_loss<<<1, 160>>>((float*)d_out);             // 7
}

// round 16
// speedup vs baseline: 1.0736x; 1.0736x over previous
#include <cuda_runtime.h>
#include <cuda_bf16.h>
#include <cstdint>

// Problem constants: B=1, C=512, H=W=64, patch 3x3 reflect-padded.
#define HW    4096
#define NC    512
#define KT    1536          // 3-term bf16 split: [hi|lo|hi] x [hi|hi|lo]
#define BM    128
#define BN    128
#define BKC   16
#define KSPL  16            // split-K factor for gram
#define NTILE 10            // triangular 128x128 tiles of 512x512

// k_mma: block 128(m) x 128(n), 8 warps as 2(m) x 4(n), warp tile 64x32,
// BK=64, 3-stage cp.async, 2 CTAs/SM.
#define MMA_BM 128
#define MMA_BN 128
#define STAGES 3
#define LDA    72           // padded smem row (bf16): 64 data + 8 pad = 144B

typedef unsigned long long u64;

// ---------------- scratch (static __device__, no allocation) ----------------
__device__ __align__(16) float g_ssP[16][2][HW];   // 32-channel-group ss partials
__device__ __align__(16) float g_cnorm[HW];
__device__ __align__(16) float g_snorm[HW];
__device__ int   g_idx[HW];
__device__ __align__(128) __nv_bfloat16 g_Abf[(size_t)HW * KT];   // content split, m-major
__device__ __align__(128) __nv_bfloat16 g_Bbf[(size_t)HW * KT];   // style split, n-major
__device__ __align__(16) float g_P[(size_t)HW * HW];              // C^T S scores (64 MB)
__device__ __align__(16) float g_Y[NC * 2 * HW];
__device__ __align__(16) float g_Gp[KSPL * NTILE * BM * BN];
__device__ __align__(16) float g_partial[NTILE * KSPL];
__device__ float g_msum;

__device__ __forceinline__ int refl(int t) {
    return t < 0 ? -t : (t >= 64 ? 126 - t : t);
}

// packed fp32x2 helpers (gram kernels)
__device__ __forceinline__ u64 pk2(float x) {
    u64 r;
    asm("mov.b64 %0, {%1, %1};" : "=l"(r) : "r"(__float_as_uint(x)));
    return r;
}
__device__ __forceinline__ void ffma2(u64& d, u64 a, u64 b) {
    asm("fma.rn.f32x2 %0, %1, %2, %0;" : "+l"(d) : "l"(a), "l"(b));
}
__device__ __forceinline__ float lo32(u64 v) { return __uint_as_float((unsigned)v); }
__device__ __forceinline__ float hi32(u64 v) { return __uint_as_float((unsigned)(v >> 32)); }

__device__ __forceinline__ uint32_t smem_u32(const void* p) {
    uint32_t a;
    asm("{ .reg .u64 t; cvta.to.shared.u64 t, %1; cvt.u32.u64 %0, t; }" : "=r"(a) : "l"(p));
    return a;
}
__device__ __forceinline__ void cp16(uint32_t saddr, const void* g) {
    asm volatile("cp.async.cg.shared.global [%0], [%1], 16;" :: "r"(saddr), "l"(g));
}

// ---------------- 0) bf16 split + transpose + fused ss partials -------------
__global__ void k_conv(const float* __restrict__ Cf, const float* __restrict__ Sf) {
    __shared__ float tile[32][33];
    const int which = blockIdx.z;
    const float* src = which ? Sf : Cf;
    __nv_bfloat16* dst = which ? g_Bbf : g_Abf;
    const int m0 = blockIdx.x * 32, c0 = blockIdx.y * 32;
    const int tx = threadIdx.x, ty = threadIdx.y;   // 32 x 8

    #pragma unroll
    for (int r = 0; r < 4; ++r)
        tile[ty + 8 * r][tx] = src[(size_t)(c0 + ty + 8 * r) * HW + m0 + tx];
    __syncthreads();
    #pragma unroll
    for (int r = 0; r < 4; ++r) {
        const int m = m0 + ty + 8 * r;
        const int c = c0 + tx;
        const float x = tile[tx][ty + 8 * r];
        const __nv_bfloat16 hi = __float2bfloat16(x);
        const __nv_bfloat16 lo = __float2bfloat16(x - __bfloat162float(hi));
        __nv_bfloat16* row = dst + (size_t)m * KT;
        if (which == 0) {       // A' = [hi | lo | hi]
            row[c] = hi; row[512 + c] = lo; row[1024 + c] = hi;
        } else {                // B' = [hi | hi | lo]
            row[c] = hi; row[512 + c] = hi; row[1024 + c] = lo;
        }
        float s = x * x;
        #pragma unroll
        for (int o = 16; o > 0; o >>= 1)
            s += __shfl_down_sync(0xffffffffu, s, o);
        if (tx == 0) g_ssP[blockIdx.y][which][m] = s;
    }
}

// ---------------- 1) patch norms + mask sum (merged) ------------------------
__global__ void k_norm(const float* __restrict__ Mk) {
    const int b = blockIdx.x;
    const int t = threadIdx.x;
    if (b < 16) {
        const int i = b * 256 + t;
        const int yy = i >> 6, xx = i & 63;
        float sc = 0.f, ss = 0.f;
        #pragma unroll
        for (int dh = -1; dh <= 1; ++dh)
            #pragma unroll
            for (int dw = -1; dw <= 1; ++dw) {
                const int p = refl(yy + dh) * 64 + refl(xx + dw);
                float a = 0.f, c = 0.f;
                #pragma unroll
                for (int s = 0; s < 16; ++s) {
                    a += g_ssP[s][0][p];
                    c += g_ssP[s][1][p];
                }
                sc += a;
                ss += c;
            }
        g_cnorm[i] = sqrtf(sc);
        g_snorm[i] = sqrtf(ss);
    } else {
        __shared__ float red[256];
        float s = 0.f;
        #pragma unroll
        for (int k = 0; k < 16; ++k) s += Mk[t + 256 * k];
        red[t] = s;
        __syncthreads();
        for (int o = 128; o > 0; o >>= 1) {
            if (t < o) red[t] += red[t + o];
            __syncthreads();
        }
        if (t == 0) g_msum = red[0];
    }
}

// ---------------- 2) P = A' B'^T via mma.sync bf16, BK=64, 3-stage ---------
#define ASZ (MMA_BM * LDA)            // 9216 elems per A stage buffer
#define BSZ (MMA_BN * LDA)
#define SMEM_MMA_BYTES ((STAGES * (ASZ + BSZ)) * 2)   // 110592 bytes

__global__ __launch_bounds__(256, 2) void k_mma() {
    extern __shared__ __nv_bfloat16 smem[];

    const int tid = threadIdx.x, wid = tid >> 5, lane = tid & 31;
    const int i0 = blockIdx.x * MMA_BM, j0 = blockIdx.y * MMA_BN;
    const int wm = (wid >> 2) * 64, wn = (wid & 3) * 32;

    const int lrow = tid >> 3, lseg = tid & 7;
    const __nv_bfloat16* gA = g_Abf + (size_t)(i0 + lrow) * KT + lseg * 8;
    const __nv_bfloat16* gB = g_Bbf + (size_t)(j0 + lrow) * KT + lseg * 8;
    const int so = lrow * LDA + lseg * 8;

    uint32_t sA[STAGES], sB[STAGES];
    #pragma unroll
    for (int st = 0; st < STAGES; ++st) {
        sA[st] = smem_u32(smem + st * (ASZ + BSZ));
        sB[st] = smem_u32(smem + st * (ASZ + BSZ) + ASZ);
    }

    const int a_r = lane & 15, a_c8 = (lane >> 4) * 8;                          // A x4
    const int b_r = (lane >> 4) * 8 + (lane & 7), b_c8 = ((lane >> 3) & 1) * 8; // B x4 (n16)

    float acc[4][4][4];
    #pragma unroll
    for (int mf = 0; mf < 4; ++mf)
        #pragma unroll
        for (int nf = 0; nf < 4; ++nf)
            #pragma unroll
            for (int q = 0; q < 4; ++q) acc[mf][nf][q] = 0.f;

    const int NSTAGE = KT / 64;   // 24

    #pragma unroll
    for (int s = 0; s < STAGES - 1; ++s) {
        const int cb = s * 64;
        const uint32_t a0 = sA[s] + (uint32_t)(so * 2);
        const uint32_t b0 = sB[s] + (uint32_t)(so * 2);
        #pragma unroll
        for (int r = 0; r < 4; ++r) {
            cp16(a0 + r * 32 * LDA * 2, gA + cb + (size_t)(r * 32) * KT);
            cp16(b0 + r * 32 * LDA * 2, gB + cb + (size_t)(r * 32) * KT);
        }
        asm volatile("cp.async.commit_group;" ::: "memory");
    }

    for (int s = 0; s < NSTAGE; ++s) {
        asm volatile("cp.async.wait_group %0;" :: "n"(STAGES - 2) : "memory");
        __syncthreads();

        if (s + STAGES - 1 < NSTAGE) {
            const int ns = s + STAGES - 1;
            const int buf = ns % STAGES;
            const int cb = ns * 64;
            const uint32_t a0 = sA[buf] + (uint32_t)(so * 2);
            const uint32_t b0 = sB[buf] + (uint32_t)(so * 2);
            #pragma unroll
            for (int r = 0; r < 4; ++r) {
                cp16(a0 + r * 32 * LDA * 2, gA + cb + (size_t)(r * 32) * KT);
                cp16(b0 + r * 32 * LDA * 2, gB + cb + (size_t)(r * 32) * KT);
            }
        }
        asm volatile("cp.async.commit_group;" ::: "memory");

        const int cur = s % STAGES;
        #pragma unroll
        for (int k0 = 0; k0 < 64; k0 += 16) {
            uint32_t b[4][2];
            #pragma unroll
            for (int np = 0; np < 2; ++np) {
                const uint32_t addr = sB[cur] +
                    (uint32_t)(((wn + np * 16 + b_r) * LDA + k0 + b_c8) * 2);
                asm volatile("ldmatrix.sync.aligned.m8n8.x4.shared.b16 {%0, %1, %2, %3}, [%4];"
                             : "=r"(b[2 * np][0]), "=r"(b[2 * np][1]),
                               "=r"(b[2 * np + 1][0]), "=r"(b[2 * np + 1][1])
                             : "r"(addr));
            }
            #pragma unroll
            for (int mf = 0; mf < 4; ++mf) {
                uint32_t a0, a1, a2, a3;
                const uint32_t addr = sA[cur] +
                    (uint32_t)(((wm + mf * 16 + a_r) * LDA + k0 + a_c8) * 2);
                asm volatile("ldmatrix.sync.aligned.m8n8.x4.shared.b16 {%0, %1, %2, %3}, [%4];"
                             : "=r"(a0), "=r"(a1), "=r"(a2), "=r"(a3) : "r"(addr));
                #pragma unroll
                for (int nf = 0; nf < 4; ++nf) {
                    asm volatile(
                        "mma.sync.aligned.m16n8k16.row.col.f32.bf16.bf16.f32 "
                        "{%0, %1, %2, %3}, {%4, %5, %6, %7}, {%8, %9}, {%0, %1, %2, %3};"
                        : "+f"(acc[mf][nf][0]), "+f"(acc[mf][nf][1]),
                          "+f"(acc[mf][nf][2]), "+f"(acc[mf][nf][3])
                        : "r"(a0), "r"(a1), "r"(a2), "r"(a3),
                          "r"(b[nf][0]), "r"(b[nf][1]));
                }
            }
        }
    }

    const int er = lane >> 2, ec = (lane & 3) * 2;
    #pragma unroll
    for (int mf = 0; mf < 4; ++mf) {
        const int row = i0 + wm + mf * 16 + er;
        #pragma unroll
        for (int nf = 0; nf < 4; ++nf) {
            const int col = j0 + wn + nf * 8 + ec;
            *(float2*)&g_P[(size_t)row * HW + col] =
                make_float2(acc[mf][nf][0], acc[mf][nf][1]);
            *(float2*)&g_P[(size_t)(row + 8) * HW + col] =
                make_float2(acc[mf][nf][2], acc[mf][nf][3]);
        }
    }
}

// ---------------- 3) 9-shift aggregate + argmax (pixel-pair per block) ------
// Block handles content pixels i = iy*64+ix0 and i+1; 12 unique P-rows shared.
__global__ __launch_bounds__(256) void k_agg() {
    __shared__ float sv[2][256];
    __shared__ int   si[2][256];
    const int t = threadIdx.x;
    const int bi = blockIdx.x;              // 0..2047
    const int iy = bi >> 5, ix0 = (bi & 31) * 2;

    // 12 row pointers: rows (dh 0..2, e 0..3), e -> image col refl(ix0-1+e)
    const float* rowp[3][4];
    #pragma unroll
    for (int dh = 0; dh < 3; ++dh) {
        const int ry = refl(iy + dh - 1) * 64;
        #pragma unroll
        for (int e = 0; e < 4; ++e)
            rowp[dh][e] = g_P + ((size_t)(ry + refl(ix0 - 1 + e)) << 12);
    }
    const float cn0 = g_cnorm[iy * 64 + ix0];
    const float cn1 = g_cnorm[iy * 64 + ix0 + 1];

    const int jx = t & 63;
    const int cxj[3] = { refl(jx - 1), jx, refl(jx + 1) };

    float bv0 = -1e30f, bv1 = -1e30f;
    int   bi0 = 0x7fffffff, bi1 = 0x7fffffff;
    for (int u = 0; u < 16; ++u) {
        const int j = u * 256 + t;
        const int jy = j >> 6;
        const int ry[3] = { refl(jy - 1) * 64, jy * 64, refl(jy + 1) * 64 };
        float a0 = 0.f, a1 = 0.f;
        #pragma unroll
        for (int dh = 0; dh < 3; ++dh)
            #pragma unroll
            for (int dw = 0; dw < 3; ++dw) {
                const int col = ry[dh] + cxj[dw];
                a0 += __ldg(&rowp[dh][dw][col]);
                a1 += __ldg(&rowp[dh][dw + 1][col]);
            }
        const float v0 = __fdividef(a0, cn0 * g_snorm[j] + 1e-9f);
        const float v1 = __fdividef(a1, cn1 * g_snorm[j] + 1e-9f);
        if (v0 > bv0) { bv0 = v0; bi0 = j; }     // j ascending -> first max wins
        if (v1 > bv1) { bv1 = v1; bi1 = j; }
    }
    sv[0][t] = bv0; si[0][t] = bi0;
    sv[1][t] = bv1; si[1][t] = bi1;
    __syncthreads();
    for (int o = 128; o > 0; o >>= 1) {
        if (t < o) {
            #pragma unroll
            for (int q = 0; q < 2; ++q) {
                const float v2 = sv[q][t + o]; const int j2 = si[q][t + o];
                if (v2 > sv[q][t] || (v2 == sv[q][t] && j2 < si[q][t])) {
                    sv[q][t] = v2; si[q][t] = j2;
                }
            }
        }
        __syncthreads();
    }
    if (t < 2) g_idx[iy * 64 + ix0 + t] = si[t][0];
}

// ---------------- 4) build Y ----------------
__global__ void k_gather(const float* __restrict__ Sf, const float* __restrict__ If,
                         const float* __restrict__ Mk) {
    int e = blockIdx.x * 256 + threadIdx.x;
    int c = e >> 13, k = e & 8191;
    if (k < HW) {
        g_Y[e] = If[(c << 12) + k] * Mk[k];
    } else {
        int j = k - HW;
        g_Y[e] = Sf[(c << 12) + g_idx[j]] * Mk[j];
    }
}

// ---------------- 5a) split-K signed gram partials (coalesced loader) -------
__constant__ int c_bx[NTILE] = {0,0,0,0,1,1,1,2,2,3};
__constant__ int c_by[NTILE] = {0,1,2,3,1,2,3,2,3,3};

__global__ __launch_bounds__(256, 2) void k_gramp() {
    __shared__ __align__(16) float Asg[BKC][BM + 4];
    __shared__ __align__(16) float Bsg[BKC][BN + 4];

    const int t  = threadIdx.x;
    const int tx = t & 15, ty = t >> 4;
    const int m0 = c_bx[blockIdx.x] * BM;
    const int n0 = c_by[blockIdx.x] * BN;
    const int kbase = blockIdx.y * (2 * HW / KSPL);
    const float sgn = (kbase >= HW) ? -1.0f : 1.0f;

    const int kk = t & 15;
    const int mr = t >> 4;

    u64 acc[8][4];
    #pragma unroll
    for (int mi = 0; mi < 8; ++mi)
        #pragma unroll
        for (int p = 0; p < 4; ++p) acc[mi][p] = 0ull;

    for (int k0 = kbase; k0 < kbase + 2 * HW / KSPL; k0 += BKC) {
        #pragma unroll
        for (int r = 0; r < 8; ++r) {
            const int row = mr + 16 * r;
            Asg[kk][row] = g_Y[(size_t)(m0 + row) * (2 * HW) + k0 + kk];
            Bsg[kk][row] = g_Y[(size_t)(n0 + row) * (2 * HW) + k0 + kk] * sgn;
        }
        __syncthreads();
        #pragma unroll
        for (int k = 0; k < BKC; ++k) {
            const float4 a0 = *(const float4*)&Asg[k][ty << 2];
            const float4 a1 = *(const float4*)&Asg[k][64 + (ty << 2)];
            const ulonglong2 b0 = *(const ulonglong2*)&Bsg[k][tx << 2];
            const ulonglong2 b1 = *(const ulonglong2*)&Bsg[k][64 + (tx << 2)];
            const u64 p0 = pk2(a0.x), p1 = pk2(a0.y), p2 = pk2(a0.z), p3 = pk2(a0.w);
            const u64 p4 = pk2(a1.x), p5 = pk2(a1.y), p6 = pk2(a1.z), p7 = pk2(a1.w);
            ffma2(acc[0][0], p0, b0.x); ffma2(acc[0][1], p0, b0.y);
            ffma2(acc[0][2], p0, b1.x); ffma2(acc[0][3], p0, b1.y);
            ffma2(acc[1][0], p1, b0.x); ffma2(acc[1][1], p1, b0.y);
            ffma2(acc[1][2], p1, b1.x); ffma2(acc[1][3], p1, b1.y);
            ffma2(acc[2][0], p2, b0.x); ffma2(acc[2][1], p2, b0.y);
            ffma2(acc[2][2], p2, b1.x); ffma2(acc[2][3], p2, b1.y);
            ffma2(acc[3][0], p3, b0.x); ffma2(acc[3][1], p3, b0.y);
            ffma2(acc[3][2], p3, b1.x); ffma2(acc[3][3], p3, b1.y);
            ffma2(acc[4][0], p4, b0.x); ffma2(acc[4][1], p4, b0.y);
            ffma2(acc[4][2], p4, b1.x); ffma2(acc[4][3], p4, b1.y);
            ffma2(acc[5][0], p5, b0.x); ffma2(acc[5][1], p5, b0.y);
            ffma2(acc[5][2], p5, b1.x); ffma2(acc[5][3], p5, b1.y);
            ffma2(acc[6][0], p6, b0.x); ffma2(acc[6][1], p6, b0.y);
            ffma2(acc[6][2], p6, b1.x); ffma2(acc[6][3], p6, b1.y);
            ffma2(acc[7][0], p7, b0.x); ffma2(acc[7][1], p7, b0.y);
            ffma2(acc[7][2], p7, b1.x); ffma2(acc[7][3], p7, b1.y);
        }
        __syncthreads();
    }

    float* dst = g_Gp + ((size_t)(blockIdx.y * NTILE + blockIdx.x) << 14);
    #pragma unroll
    for (int mi = 0; mi < 8; ++mi) {
        const int m_local = (mi < 4) ? (ty << 2) + mi : 64 + (ty << 2) + (mi - 4);
        #pragma unroll
        for (int p = 0; p < 4; ++p) {
            const int nb = (p < 2) ? (tx << 2) + 2 * p : 64 + (tx << 2) + 2 * (p - 2);
            *(float2*)&dst[m_local * BN + nb] = make_float2(lo32(acc[mi][p]), hi32(acc[mi][p]));
        }
    }
}

// ---------------- 5b) reduce split-K partials ----------------
__global__ void k_gramr() {
    __shared__ float red[256];
    const int t = threadIdx.x;
    const int tile = blockIdx.x;
    const int e0 = blockIdx.y * 1024 + t * 4;
    const float w = (c_bx[tile] == c_by[tile]) ? 1.0f : 2.0f;

    float4 d = make_float4(0.f, 0.f, 0.f, 0.f);
    #pragma unroll
    for (int ks = 0; ks < KSPL; ++ks) {
        const float4 v = *(const float4*)&g_Gp[((size_t)(ks * NTILE + tile) << 14) + e0];
        d.x += v.x; d.y += v.y; d.z += v.z; d.w += v.w;
    }
    red[t] = (d.x * d.x + d.y * d.y + d.z * d.z + d.w * d.w) * w;
    __syncthreads();
    for (int o = 128; o > 0; o >>= 1) {
        if (t < o) red[t] += red[t + o];
        __syncthreads();
    }
    if (t == 0) g_partial[tile * 16 + blockIdx.y] = red[0];
}

// ---------------- 6) final loss ----------------
__global__ void k_loss(float* __restrict__ out) {
    __shared__ float red[160];
    int t = threadIdx.x;          // blockDim.x == 160
    red[t] = g_partial[t];
    __syncthreads();
    if (t == 0) {
        float s = 0.f;
        for (int i = 0; i < NTILE * KSPL; ++i) s += red[i];
        const float ms = g_msum;
        out[0] = s / (ms * ms) / (float)(NC * NC) * 100.0f;
    }
}

// ---------------- launch ----------------
extern "C" void kernel_launch(void* const* d_in, const int* in_sizes, int n_in,
                              void* d_out, int out_size) {
    const float* Cf = (const float*)d_in[0];
    const float* Sf = (const float*)d_in[1];
    const float* If = (const float*)d_in[2];
    const float* Mk = (const float*)d_in[3];

    static int smem_set = 0;
    if (!smem_set) {
        cudaFuncSetAttribute(k_mma, cudaFuncAttributeMaxDynamicSharedMemorySize,
                             SMEM_MMA_BYTES);
        smem_set = 1;
    }

    dim3 gc(HW / 32, NC / 32, 2);
    k_conv<<<gc, dim3(32, 8)>>>(Cf, Sf);           // 0  (ss partials fused)
    k_norm<<<17, 256>>>(Mk);                       // 1  (norm + msum merged)
    dim3 gm(HW / MMA_BM, HW / MMA_BN);
    k_mma<<<gm, 256, SMEM_MMA_BYTES>>>();          // 2
    k_agg<<<HW / 2, 256>>>();                      // 3  (ncu capture slot)
    k_gather<<<(NC * 2 * HW) / 256, 256>>>(Sf, If, Mk);  // 4
    dim3 ggp(NTILE, KSPL);
    k_gramp<<<ggp, 256>>>();                       // 5
    dim3 ggr(NTILE, 16);
    k_gramr<<<ggr, 256>>>();                       // 6
    k_loss<<<1, 160>>>((float*)d_out);             // 7
}